// round 1
// baseline (speedup 1.0000x reference)
#include <cuda_runtime.h>
#include <math.h>

// ---------------------------------------------------------------------------
// DeltaE2000 + MSE combined loss, mean over B=16.7M rows of [3] f32.
// One thread per row; two-stage deterministic reduction.
// ---------------------------------------------------------------------------

constexpr int THREADS = 256;
constexpr int BLOCKS  = 4096;

__device__ float g_partials[BLOCKS];

__device__ __forceinline__ float warp_reduce(float v) {
#pragma unroll
    for (int o = 16; o > 0; o >>= 1) v += __shfl_down_sync(0xffffffffu, v, o);
    return v;
}

__device__ __forceinline__ float pow7(float x) {
    float x2 = x * x;
    float x4 = x2 * x2;
    return x4 * x2 * x;
}

__device__ __forceinline__ float srgb_lin(float c) {
    // c in [0,1]
    float hi = __powf((c + 0.055f) * (1.0f / 1.055f), 2.4f);
    float lo = c * (1.0f / 12.92f);
    return (c > 0.04045f) ? hi : lo;
}

__device__ __forceinline__ float lab_f(float t) {
    // t >= 0
    float hi = __powf(t, 1.0f / 3.0f);
    float lo = 7.787f * t + 16.0f / 116.0f;
    return (t > 0.008856f) ? hi : lo;
}

__device__ __forceinline__ void rgb2lab(float r, float g, float b,
                                        float& L, float& A, float& Bo) {
    float lr = srgb_lin(r);
    float lg = srgb_lin(g);
    float lb = srgb_lin(b);
    // XYZ matrix with white-point division folded in (compile-time folded)
    float xn = (0.4124564f / 0.95047f) * lr + (0.3575761f / 0.95047f) * lg + (0.1804375f / 0.95047f) * lb;
    float yn = 0.2126729f * lr + 0.7151522f * lg + 0.072175f * lb;
    float zn = (0.0193339f / 1.08883f) * lr + (0.119192f / 1.08883f) * lg + (0.9503041f / 1.08883f) * lb;
    float fx = lab_f(xn);
    float fy = lab_f(yn);
    float fz = lab_f(zn);
    L  = 116.0f * fy - 16.0f;
    A  = 500.0f * (fx - fy);
    Bo = 200.0f * (fy - fz);
}

__device__ __forceinline__ float delta_e_2000(float L1, float a1, float b1,
                                              float L2, float a2, float b2) {
    const float PI_F    = 3.14159265358979323846f;
    const float TWO_PI_F = 6.28318530717958647692f;
    const float POW25_7 = 6103515625.0f;  // 25^7

    float C1 = sqrtf(a1 * a1 + b1 * b1);
    float C2 = sqrtf(a2 * a2 + b2 * b2);
    float Cavg = 0.5f * (C1 + C2);
    float Cavg7 = pow7(Cavg);
    float G = 0.5f * (1.0f - sqrtf(__fdividef(Cavg7, Cavg7 + POW25_7)));
    float a1p = a1 * (1.0f + G);
    float a2p = a2 * (1.0f + G);
    float C1p = sqrtf(a1p * a1p + b1 * b1);
    float C2p = sqrtf(a2p * a2p + b2 * b2);
    float h1p = atan2f(b1, a1p); if (h1p < 0.0f) h1p += TWO_PI_F;
    float h2p = atan2f(b2, a2p); if (h2p < 0.0f) h2p += TWO_PI_F;

    float dL = L2 - L1;
    float dC = C2p - C1p;
    float dh = h2p - h1p;
    if (fabsf(dh) > PI_F) dh += (h2p <= h1p) ? TWO_PI_F : -TWO_PI_F;
    float dH = 2.0f * sqrtf(C1p * C2p) * __sinf(0.5f * dh);

    float Lavg = 0.5f * (L1 + L2);
    float Cpavg = 0.5f * (C1p + C2p);
    float hsum = h1p + h2p;
    float havg = (fabsf(h1p - h2p) > PI_F) ? 0.5f * (hsum + TWO_PI_F) : 0.5f * hsum;

    float T = 1.0f
            - 0.17f * __cosf(havg - PI_F / 6.0f)
            + 0.24f * __cosf(2.0f * havg)
            + 0.32f * __cosf(3.0f * havg + PI_F / 30.0f)
            - 0.20f * __cosf(4.0f * havg - 7.0f * PI_F / 20.0f);

    float hdeg = havg * (180.0f / PI_F);
    float u = (hdeg - 275.0f) * (1.0f / 25.0f);
    float theta = 30.0f * __expf(-u * u);

    float Cp7 = pow7(Cpavg);
    float RC = 2.0f * sqrtf(__fdividef(Cp7, Cp7 + POW25_7));
    // NOTE: reference calls jnp.sin on the degree-valued theta (radians arg up
    // to ~60) — we reproduce that exactly. sinf handles full range reduction.
    float RT = -sinf(2.0f * theta) * RC;

    float Lm = Lavg - 50.0f;
    float Lm2 = Lm * Lm;
    float SL = 1.0f + 0.015f * Lm2 * rsqrtf(20.0f + Lm2);
    float SC = 1.0f + 0.045f * Cpavg;
    float SH = 1.0f + 0.015f * Cpavg * T;

    float x = __fdividef(dL, SL);
    float y = __fdividef(dC, SC);
    float z = __fdividef(dH, SH);
    return sqrtf(x * x + y * y + z * z + RT * y * z);
}

__global__ void __launch_bounds__(THREADS)
de_loss_kernel(const float* __restrict__ pred, const float* __restrict__ targ, int n) {
    float acc = 0.0f;
    for (int i = blockIdx.x * blockDim.x + threadIdx.x; i < n;
         i += gridDim.x * blockDim.x) {
        int base = 3 * i;
        float pr = pred[base + 0], pg = pred[base + 1], pb = pred[base + 2];
        float tr = targ[base + 0], tg = targ[base + 1], tb = targ[base + 2];

        float d0 = pr - tr, d1 = pg - tg, d2 = pb - tb;
        float mse = (d0 * d0 + d1 * d1 + d2 * d2) * (1.0f / 3.0f);

        float L1, A1, B1, L2, A2, B2;
        rgb2lab(pr, pg, pb, L1, A1, B1);
        rgb2lab(tr, tg, tb, L2, A2, B2);
        float de = delta_e_2000(L1, A1, B1, L2, A2, B2);

        acc += 0.2f * mse + 0.8f * de;
    }

    // Block reduction
    float v = warp_reduce(acc);
    __shared__ float sh[THREADS / 32];
    int lane = threadIdx.x & 31;
    int wid = threadIdx.x >> 5;
    if (lane == 0) sh[wid] = v;
    __syncthreads();
    if (wid == 0) {
        v = (lane < THREADS / 32) ? sh[lane] : 0.0f;
        v = warp_reduce(v);
        if (lane == 0) g_partials[blockIdx.x] = v;
    }
}

__global__ void __launch_bounds__(256)
finalize_kernel(float* __restrict__ out, float inv_n) {
    float acc = 0.0f;
    for (int i = threadIdx.x; i < BLOCKS; i += 256) acc += g_partials[i];
    float v = warp_reduce(acc);
    __shared__ float sh[8];
    int lane = threadIdx.x & 31;
    int wid = threadIdx.x >> 5;
    if (lane == 0) sh[wid] = v;
    __syncthreads();
    if (wid == 0) {
        v = (lane < 8) ? sh[lane] : 0.0f;
        v = warp_reduce(v);
        if (lane == 0) out[0] = v * inv_n;
    }
}

extern "C" void kernel_launch(void* const* d_in, const int* in_sizes, int n_in,
                              void* d_out, int out_size) {
    const float* pred = (const float*)d_in[0];
    const float* targ = (const float*)d_in[1];
    int n = in_sizes[0] / 3;
    de_loss_kernel<<<BLOCKS, THREADS>>>(pred, targ, n);
    finalize_kernel<<<1, 256>>>((float*)d_out, 1.0f / (float)n);
}

// round 2
// speedup vs baseline: 1.1506x; 1.1506x over previous
#include <cuda_runtime.h>
#include <math.h>

// ---------------------------------------------------------------------------
// DeltaE2000 + MSE combined loss, mean over B=16.7M rows of [3] f32.
// Single fused kernel: float4 loads (4 rows/iter), fast intrinsic math,
// custom atan2, last-block reduction (no second kernel).
// ---------------------------------------------------------------------------

constexpr int THREADS = 256;
constexpr int BLOCKS  = 4096;

__device__ float g_partials[BLOCKS];
__device__ unsigned int g_count = 0;

__device__ __forceinline__ float warp_reduce(float v) {
#pragma unroll
    for (int o = 16; o > 0; o >>= 1) v += __shfl_down_sync(0xffffffffu, v, o);
    return v;
}

__device__ __forceinline__ float pow7(float x) {
    float x2 = x * x;
    float x4 = x2 * x2;
    return x4 * x2 * x;
}

__device__ __forceinline__ float srgb_lin(float c) {
    float hi = __powf((c + 0.055f) * (1.0f / 1.055f), 2.4f);
    float lo = c * (1.0f / 12.92f);
    return (c > 0.04045f) ? hi : lo;
}

__device__ __forceinline__ float lab_f(float t) {
    float hi = __powf(t, 1.0f / 3.0f);
    float lo = 7.787f * t + 16.0f / 116.0f;
    return (t > 0.008856f) ? hi : lo;
}

__device__ __forceinline__ void rgb2lab(float r, float g, float b,
                                        float& L, float& A, float& Bo) {
    float lr = srgb_lin(r);
    float lg = srgb_lin(g);
    float lb = srgb_lin(b);
    float xn = (0.4124564f / 0.95047f) * lr + (0.3575761f / 0.95047f) * lg + (0.1804375f / 0.95047f) * lb;
    float yn = 0.2126729f * lr + 0.7151522f * lg + 0.072175f * lb;
    float zn = (0.0193339f / 1.08883f) * lr + (0.119192f / 1.08883f) * lg + (0.9503041f / 1.08883f) * lb;
    float fx = lab_f(xn);
    float fy = lab_f(yn);
    float fz = lab_f(zn);
    L  = 116.0f * fy - 16.0f;
    A  = 500.0f * (fx - fy);
    Bo = 200.0f * (fy - fz);
}

// Fast atan2: deg-11 odd minimax poly on [0,1] + quadrant fixup. ~2e-6 rad err.
__device__ __forceinline__ float fast_atan2(float y, float x) {
    float ax = fabsf(x), ay = fabsf(y);
    float mx = fmaxf(ax, ay), mn = fminf(ax, ay);
    float t = __fdividef(mn, fmaxf(mx, 1e-38f));
    float t2 = t * t;
    float p = fmaf(t2, -0.01172120f, 0.05265332f);
    p = fmaf(t2, p, -0.11643287f);
    p = fmaf(t2, p, 0.19354346f);
    p = fmaf(t2, p, -0.33262347f);
    p = fmaf(t2, p, 0.99997726f);
    float r = p * t;
    if (ay > ax)   r = 1.5707963267948966f - r;
    if (x < 0.0f)  r = 3.1415926535897932f - r;
    return copysignf(r, y);
}

__device__ __forceinline__ float delta_e_2000(float L1, float a1, float b1,
                                              float L2, float a2, float b2) {
    const float PI_F     = 3.14159265358979323846f;
    const float TWO_PI_F = 6.28318530717958647692f;
    const float POW25_7  = 6103515625.0f;

    float C1 = sqrtf(fmaf(a1, a1, b1 * b1));
    float C2 = sqrtf(fmaf(a2, a2, b2 * b2));
    float Cavg = 0.5f * (C1 + C2);
    float Cavg7 = pow7(Cavg);
    float G = 0.5f * (1.0f - sqrtf(__fdividef(Cavg7, Cavg7 + POW25_7)));
    float a1p = a1 * (1.0f + G);
    float a2p = a2 * (1.0f + G);
    float C1p = sqrtf(fmaf(a1p, a1p, b1 * b1));
    float C2p = sqrtf(fmaf(a2p, a2p, b2 * b2));
    float h1p = fast_atan2(b1, a1p); if (h1p < 0.0f) h1p += TWO_PI_F;
    float h2p = fast_atan2(b2, a2p); if (h2p < 0.0f) h2p += TWO_PI_F;

    float dL = L2 - L1;
    float dC = C2p - C1p;
    float dh = h2p - h1p;
    if (fabsf(dh) > PI_F) dh += (h2p <= h1p) ? TWO_PI_F : -TWO_PI_F;
    float dH = 2.0f * sqrtf(C1p * C2p) * __sinf(0.5f * dh);

    float Lavg = 0.5f * (L1 + L2);
    float Cpavg = 0.5f * (C1p + C2p);
    float hsum = h1p + h2p;
    float havg = (fabsf(h1p - h2p) > PI_F) ? 0.5f * (hsum + TWO_PI_F) : 0.5f * hsum;

    // T via angle-addition from a single sincos(havg)
    float sh, ch;
    __sincosf(havg, &sh, &ch);
    float c2 = fmaf(2.0f * ch, ch, -1.0f);     // cos 2h
    float s2 = 2.0f * sh * ch;                 // sin 2h
    float c3 = c2 * ch - s2 * sh;              // cos 3h
    float s3 = s2 * ch + c2 * sh;              // sin 3h
    float c4 = fmaf(2.0f * c2, c2, -1.0f);     // cos 4h
    float s4 = 2.0f * s2 * c2;                 // sin 4h
    // cos(h - pi/6), cos(3h + pi/30), cos(4h - 7pi/20)
    const float C_P6 = 0.86602540378443865f, S_P6 = 0.5f;            // cos,sin pi/6
    const float C_P30 = 0.99452189536827329f, S_P30 = 0.10452846326765347f; // pi/30
    const float C_7P20 = 0.45399049973954680f, S_7P20 = 0.89100652418836786f; // 7pi/20
    float T = 1.0f
            - 0.17f * fmaf(ch, C_P6, sh * S_P6)
            + 0.24f * c2
            + 0.32f * fmaf(c3, C_P30, -s3 * S_P30)
            - 0.20f * fmaf(c4, C_7P20, s4 * S_7P20);

    float hdeg = havg * (180.0f / PI_F);
    float u = (hdeg - 275.0f) * (1.0f / 25.0f);
    float theta = 30.0f * __expf(-u * u);

    float Cp7 = pow7(Cpavg);
    float RC = 2.0f * sqrtf(__fdividef(Cp7, Cp7 + POW25_7));
    // sin(2*theta), arg in [0,60]: one Cody-Waite step then fast sin
    float x2t = 2.0f * theta;
    float k = rintf(x2t * 0.15915494309189535f);
    float xr = fmaf(-k, 6.2831855f, x2t);
    xr = fmaf(-k, -1.7484555e-7f, xr);
    float RT = -__sinf(xr) * RC;

    float Lm = Lavg - 50.0f;
    float Lm2 = Lm * Lm;
    float SL = 1.0f + 0.015f * Lm2 * rsqrtf(20.0f + Lm2);
    float SC = fmaf(0.045f, Cpavg, 1.0f);
    float SH = fmaf(0.015f, Cpavg * T, 1.0f);

    float xx = __fdividef(dL, SL);
    float yy = __fdividef(dC, SC);
    float zz = __fdividef(dH, SH);
    return sqrtf(fmaf(xx, xx, fmaf(yy, yy, fmaf(zz, zz, RT * yy * zz))));
}

__device__ __forceinline__ float row_loss(float pr, float pg, float pb,
                                          float tr, float tg, float tb) {
    float d0 = pr - tr, d1 = pg - tg, d2 = pb - tb;
    float mse = (fmaf(d0, d0, fmaf(d1, d1, d2 * d2))) * (1.0f / 3.0f);
    float L1, A1, B1, L2, A2, B2;
    rgb2lab(pr, pg, pb, L1, A1, B1);
    rgb2lab(tr, tg, tb, L2, A2, B2);
    float de = delta_e_2000(L1, A1, B1, L2, A2, B2);
    return fmaf(0.2f, mse, 0.8f * de);
}

__global__ void __launch_bounds__(THREADS)
de_loss_kernel(const float* __restrict__ pred, const float* __restrict__ targ,
               float* __restrict__ out, int n, float inv_n) {
    const int P = gridDim.x * blockDim.x;
    const int tid = blockIdx.x * blockDim.x + threadIdx.x;
    float acc = 0.0f;

    // 4 rows per iteration via 3 float4 loads per array
    for (int base = tid * 4; base + 3 < n; base += P * 4) {
        const float4* p4 = reinterpret_cast<const float4*>(pred + (size_t)base * 3);
        const float4* t4 = reinterpret_cast<const float4*>(targ + (size_t)base * 3);
        float4 p0 = p4[0], p1 = p4[1], p2 = p4[2];
        float4 q0 = t4[0], q1 = t4[1], q2 = t4[2];

        acc += row_loss(p0.x, p0.y, p0.z,  q0.x, q0.y, q0.z);
        acc += row_loss(p0.w, p1.x, p1.y,  q0.w, q1.x, q1.y);
        acc += row_loss(p1.z, p1.w, p2.x,  q1.z, q1.w, q2.x);
        acc += row_loss(p2.y, p2.z, p2.w,  q2.y, q2.z, q2.w);
    }
    // tail (n not multiple of 4*P handled per-row; B=16.7M is exact multiple)
    int tail_start = (n / (P * 4)) * (P * 4);
    for (int i = tail_start + tid; i < n; i += P) {
        if (i >= tail_start + (n - tail_start)) break;
        const float* p = pred + (size_t)i * 3;
        const float* t = targ + (size_t)i * 3;
        acc += row_loss(p[0], p[1], p[2], t[0], t[1], t[2]);
    }

    // block reduction
    float v = warp_reduce(acc);
    __shared__ float sh[THREADS / 32];
    int lane = threadIdx.x & 31;
    int wid = threadIdx.x >> 5;
    if (lane == 0) sh[wid] = v;
    __syncthreads();
    if (wid == 0) {
        v = (lane < THREADS / 32) ? sh[lane] : 0.0f;
        v = warp_reduce(v);
        if (lane == 0) g_partials[blockIdx.x] = v;
    }

    // last-block final reduction
    __shared__ bool is_last;
    __threadfence();
    if (threadIdx.x == 0) {
        unsigned int c = atomicAdd(&g_count, 1u);
        is_last = (c == gridDim.x - 1);
    }
    __syncthreads();
    if (is_last) {
        float a = 0.0f;
        for (int i = threadIdx.x; i < BLOCKS; i += THREADS) a += g_partials[i];
        float w = warp_reduce(a);
        if (lane == 0) sh[wid] = w;
        __syncthreads();
        if (wid == 0) {
            w = (lane < THREADS / 32) ? sh[lane] : 0.0f;
            w = warp_reduce(w);
            if (lane == 0) {
                out[0] = w * inv_n;
                g_count = 0;  // reset for next (graph-replayed) call
            }
        }
    }
}

extern "C" void kernel_launch(void* const* d_in, const int* in_sizes, int n_in,
                              void* d_out, int out_size) {
    const float* pred = (const float*)d_in[0];
    const float* targ = (const float*)d_in[1];
    int n = in_sizes[0] / 3;
    de_loss_kernel<<<BLOCKS, THREADS>>>(pred, targ, (float*)d_out, n, 1.0f / (float)n);
}

// round 3
// speedup vs baseline: 1.1765x; 1.0225x over previous
#include <cuda_runtime.h>
#include <math.h>

// ---------------------------------------------------------------------------
// DeltaE2000 + MSE combined loss, mean over B=16.7M rows of [3] f32.
// Issue-bound kernel -> minimize instructions/row:
//  - all sqrt via MUFU.RSQ (x * rsqrtf(x))
//  - dH via half-angle identity (no sin, no wrap branch)
//  - G/RC via rsqrt(1 + P/C^7) (no divide+sqrt)
//  - fast poly atan2, single sincos + angle addition for T
// ---------------------------------------------------------------------------

constexpr int THREADS = 256;
constexpr int BLOCKS  = 4096;

__device__ float g_partials[BLOCKS];
__device__ unsigned int g_count = 0;

__device__ __forceinline__ float warp_reduce(float v) {
#pragma unroll
    for (int o = 16; o > 0; o >>= 1) v += __shfl_down_sync(0xffffffffu, v, o);
    return v;
}

// sqrt(x) for x >= 0 as 3 cheap instructions (RSQ + FMAX + FMUL); exact 0 -> 0.
__device__ __forceinline__ float fast_sqrt(float x) {
    return x * rsqrtf(fmaxf(x, 1e-30f));
}

__device__ __forceinline__ float pow7(float x) {
    float x2 = x * x;
    float x4 = x2 * x2;
    return x4 * x2 * x;
}

// sqrt(c7 / (c7 + P)) = rsqrt(1 + P/c7)
__device__ __forceinline__ float chroma_ratio_sqrt(float c7) {
    const float POW25_7 = 6103515625.0f;
    return rsqrtf(fmaf(POW25_7, __frcp_rn(fmaxf(c7, 1e-30f)), 1.0f));
}

__device__ __forceinline__ float srgb_lin(float c) {
    float hi = __powf((c + 0.055f) * (1.0f / 1.055f), 2.4f);
    float lo = c * (1.0f / 12.92f);
    return (c > 0.04045f) ? hi : lo;
}

__device__ __forceinline__ float lab_f(float t) {
    float hi = __powf(t, 1.0f / 3.0f);
    float lo = 7.787f * t + 16.0f / 116.0f;
    return (t > 0.008856f) ? hi : lo;
}

__device__ __forceinline__ void rgb2lab(float r, float g, float b,
                                        float& L, float& A, float& Bo) {
    float lr = srgb_lin(r);
    float lg = srgb_lin(g);
    float lb = srgb_lin(b);
    float xn = (0.4124564f / 0.95047f) * lr + (0.3575761f / 0.95047f) * lg + (0.1804375f / 0.95047f) * lb;
    float yn = 0.2126729f * lr + 0.7151522f * lg + 0.072175f * lb;
    float zn = (0.0193339f / 1.08883f) * lr + (0.119192f / 1.08883f) * lg + (0.9503041f / 1.08883f) * lb;
    float fx = lab_f(xn);
    float fy = lab_f(yn);
    float fz = lab_f(zn);
    L  = 116.0f * fy - 16.0f;
    A  = 500.0f * (fx - fy);
    Bo = 200.0f * (fy - fz);
}

// Fast atan2: deg-9 odd minimax poly on [0,1] + quadrant fixup. ~2e-6 rad err.
__device__ __forceinline__ float fast_atan2(float y, float x) {
    float ax = fabsf(x), ay = fabsf(y);
    float mx = fmaxf(ax, ay), mn = fminf(ax, ay);
    float t = __fdividef(mn, fmaxf(mx, 1e-38f));
    float t2 = t * t;
    float p = fmaf(t2, -0.01172120f, 0.05265332f);
    p = fmaf(t2, p, -0.11643287f);
    p = fmaf(t2, p, 0.19354346f);
    p = fmaf(t2, p, -0.33262347f);
    p = fmaf(t2, p, 0.99997726f);
    float r = p * t;
    if (ay > ax)   r = 1.5707963267948966f - r;
    if (x < 0.0f)  r = 3.1415926535897932f - r;
    return copysignf(r, y);
}

__device__ __forceinline__ float delta_e_2000(float L1, float a1, float b1,
                                              float L2, float a2, float b2) {
    const float PI_F     = 3.14159265358979323846f;
    const float TWO_PI_F = 6.28318530717958647692f;

    float C1 = fast_sqrt(fmaf(a1, a1, b1 * b1));
    float C2 = fast_sqrt(fmaf(a2, a2, b2 * b2));
    float Cavg = 0.5f * (C1 + C2);
    float G = 0.5f * (1.0f - chroma_ratio_sqrt(pow7(Cavg)));
    float a1p = a1 * (1.0f + G);
    float a2p = a2 * (1.0f + G);
    float C1p2 = fmaf(a1p, a1p, b1 * b1);
    float C2p2 = fmaf(a2p, a2p, b2 * b2);
    float C1p = fast_sqrt(C1p2);
    float C2p = fast_sqrt(C2p2);
    float h1p = fast_atan2(b1, a1p); if (h1p < 0.0f) h1p += TWO_PI_F;
    float h2p = fast_atan2(b2, a2p); if (h2p < 0.0f) h2p += TWO_PI_F;

    float dL = L2 - L1;
    float dC = C2p - C1p;

    // dH = 2*sqrt(C1p*C2p)*sin(dh/2) with wrapped dh in (-pi,pi]:
    //    = sign(sin dh) * sqrt(2*(C1p*C2p - (a1p*a2p + b1*b2)))
    float dot   = fmaf(a1p, a2p, b1 * b2);
    float cross = fmaf(b2, a1p, -b1 * a2p);          // C1p*C2p*sin(dh)
    float CC    = C1p * C2p;
    float dHmag = fast_sqrt(fmaxf(2.0f * (CC - dot), 0.0f));
    float dH = copysignf(dHmag, cross);

    float Lavg = 0.5f * (L1 + L2);
    float Cpavg = 0.5f * (C1p + C2p);
    float hsum = h1p + h2p;
    float havg = (fabsf(h1p - h2p) > PI_F) ? 0.5f * (hsum + TWO_PI_F) : 0.5f * hsum;

    // T via angle-addition from a single sincos(havg)
    float sh, ch;
    __sincosf(havg, &sh, &ch);
    float c2 = fmaf(2.0f * ch, ch, -1.0f);
    float s2 = 2.0f * sh * ch;
    float c3 = c2 * ch - s2 * sh;
    float s3 = s2 * ch + c2 * sh;
    float c4 = fmaf(2.0f * c2, c2, -1.0f);
    float s4 = 2.0f * s2 * c2;
    const float C_P6   = 0.86602540378443865f, S_P6   = 0.5f;
    const float C_P30  = 0.99452189536827329f, S_P30  = 0.10452846326765347f;
    const float C_7P20 = 0.45399049973954680f, S_7P20 = 0.89100652418836786f;
    float T = 1.0f
            - 0.17f * fmaf(ch, C_P6, sh * S_P6)
            + 0.24f * c2
            + 0.32f * fmaf(c3, C_P30, -s3 * S_P30)
            - 0.20f * fmaf(c4, C_7P20, s4 * S_7P20);

    float hdeg = havg * (180.0f / PI_F);
    float u = (hdeg - 275.0f) * (1.0f / 25.0f);
    float theta = 30.0f * __expf(-u * u);

    float RC = 2.0f * chroma_ratio_sqrt(pow7(Cpavg));
    // sin(2*theta), arg in [0,60]: one Cody-Waite step then fast sin
    float x2t = 2.0f * theta;
    float k = rintf(x2t * 0.15915494309189535f);
    float xr = fmaf(-k, 6.2831855f, x2t);
    xr = fmaf(-k, -1.7484555e-7f, xr);
    float RT = -__sinf(xr) * RC;

    float Lm = Lavg - 50.0f;
    float Lm2 = Lm * Lm;
    float SL = fmaf(0.015f * Lm2, rsqrtf(20.0f + Lm2), 1.0f);
    float SC = fmaf(0.045f, Cpavg, 1.0f);
    float SH = fmaf(0.015f, Cpavg * T, 1.0f);

    float xx = dL * __frcp_rn(SL);
    float yy = dC * __frcp_rn(SC);
    float zz = dH * __frcp_rn(SH);
    return fast_sqrt(fmaf(xx, xx, fmaf(yy, yy, fmaf(zz, zz, RT * yy * zz))));
}

__device__ __forceinline__ float row_loss(float pr, float pg, float pb,
                                          float tr, float tg, float tb) {
    float d0 = pr - tr, d1 = pg - tg, d2 = pb - tb;
    float mse = (fmaf(d0, d0, fmaf(d1, d1, d2 * d2))) * (1.0f / 3.0f);
    float L1, A1, B1, L2, A2, B2;
    rgb2lab(pr, pg, pb, L1, A1, B1);
    rgb2lab(tr, tg, tb, L2, A2, B2);
    float de = delta_e_2000(L1, A1, B1, L2, A2, B2);
    return fmaf(0.2f, mse, 0.8f * de);
}

__global__ void __launch_bounds__(THREADS)
de_loss_kernel(const float* __restrict__ pred, const float* __restrict__ targ,
               float* __restrict__ out, int n, float inv_n) {
    const int P = gridDim.x * blockDim.x;
    const int tid = blockIdx.x * blockDim.x + threadIdx.x;
    float acc = 0.0f;

    for (int base = tid * 4; base + 3 < n; base += P * 4) {
        const float4* p4 = reinterpret_cast<const float4*>(pred + (size_t)base * 3);
        const float4* t4 = reinterpret_cast<const float4*>(targ + (size_t)base * 3);
        float4 p0 = p4[0], p1 = p4[1], p2 = p4[2];
        float4 q0 = t4[0], q1 = t4[1], q2 = t4[2];

        acc += row_loss(p0.x, p0.y, p0.z,  q0.x, q0.y, q0.z);
        acc += row_loss(p0.w, p1.x, p1.y,  q0.w, q1.x, q1.y);
        acc += row_loss(p1.z, p1.w, p2.x,  q1.z, q1.w, q2.x);
        acc += row_loss(p2.y, p2.z, p2.w,  q2.y, q2.z, q2.w);
    }
    // tail (B = 16.7M is an exact multiple; kept for generality)
    int tail_start = (n / (P * 4)) * (P * 4);
    for (int i = tail_start + tid; i < n; i += P) {
        const float* p = pred + (size_t)i * 3;
        const float* t = targ + (size_t)i * 3;
        acc += row_loss(p[0], p[1], p[2], t[0], t[1], t[2]);
    }

    float v = warp_reduce(acc);
    __shared__ float sh[THREADS / 32];
    int lane = threadIdx.x & 31;
    int wid = threadIdx.x >> 5;
    if (lane == 0) sh[wid] = v;
    __syncthreads();
    if (wid == 0) {
        v = (lane < THREADS / 32) ? sh[lane] : 0.0f;
        v = warp_reduce(v);
        if (lane == 0) g_partials[blockIdx.x] = v;
    }

    __shared__ bool is_last;
    __threadfence();
    if (threadIdx.x == 0) {
        unsigned int c = atomicAdd(&g_count, 1u);
        is_last = (c == gridDim.x - 1);
    }
    __syncthreads();
    if (is_last) {
        float a = 0.0f;
        for (int i = threadIdx.x; i < BLOCKS; i += THREADS) a += g_partials[i];
        float w = warp_reduce(a);
        if (lane == 0) sh[wid] = w;
        __syncthreads();
        if (wid == 0) {
            w = (lane < THREADS / 32) ? sh[lane] : 0.0f;
            w = warp_reduce(w);
            if (lane == 0) {
                out[0] = w * inv_n;
                g_count = 0;
            }
        }
    }
}

extern "C" void kernel_launch(void* const* d_in, const int* in_sizes, int n_in,
                              void* d_out, int out_size) {
    const float* pred = (const float*)d_in[0];
    const float* targ = (const float*)d_in[1];
    int n = in_sizes[0] / 3;
    de_loss_kernel<<<BLOCKS, THREADS>>>(pred, targ, (float*)d_out, n, 1.0f / (float)n);
}

// round 4
// speedup vs baseline: 1.3543x; 1.1511x over previous
#include <cuda_runtime.h>
#include <math.h>

// ---------------------------------------------------------------------------
// DeltaE2000 + MSE loss. MUFU(XU)-pipe was binding (45 MUFU/row x 8cyc rt).
// This round: sRGB-linearize and Lab-f(cbrt) via shared-memory tables
// (0 MUFU), sqrt.approx/rcp.approx everywhere, merged final divides.
// ---------------------------------------------------------------------------

constexpr int THREADS = 256;
constexpr int BLOCKS  = 4096;
constexpr int SRGB_N  = 2048;
constexpr int LABF_N  = 8192;                 // 8 octaves [2^-7, 2), 1024/octave
constexpr unsigned LABF_BASE = 0x3C000000u;   // bits of 2^-7

__device__ float g_partials[BLOCKS];
__device__ unsigned int g_count = 0;
__device__ float g_srgb_tab[SRGB_N];
__device__ float g_labf_tab[LABF_N];

__global__ void init_tables_kernel() {
    int i = blockIdx.x * blockDim.x + threadIdx.x;
    if (i < SRGB_N) {
        float c = (i + 0.5f) / (float)SRGB_N;
        float hi = powf((c + 0.055f) / 1.055f, 2.4f);
        float lo = c / 12.92f;
        g_srgb_tab[i] = (c > 0.04045f) ? hi : lo;
    }
    if (i < LABF_N) {
        unsigned bits = LABF_BASE + ((unsigned)i << 13) + (1u << 12); // bucket center
        g_labf_tab[i] = cbrtf(__uint_as_float(bits));
    }
}

__device__ __forceinline__ float warp_reduce(float v) {
#pragma unroll
    for (int o = 16; o > 0; o >>= 1) v += __shfl_down_sync(0xffffffffu, v, o);
    return v;
}

__device__ __forceinline__ float fsqrt_a(float x) {
    float r; asm("sqrt.approx.f32 %0, %1;" : "=f"(r) : "f"(x)); return r;
}
__device__ __forceinline__ float frcp_a(float x) {
    float r; asm("rcp.approx.f32 %0, %1;" : "=f"(r) : "f"(x)); return r;
}

__device__ __forceinline__ float pow7(float x) {
    float x2 = x * x;
    float x4 = x2 * x2;
    return x4 * x2 * x;
}

// sqrt(c7/(c7+P)) = rsqrt(1 + P/c7); c7=0 -> rcp=inf -> rsqrt(inf)=0 (correct)
__device__ __forceinline__ float chroma_ratio_sqrt(float c7) {
    const float POW25_7 = 6103515625.0f;
    return rsqrtf(fmaf(POW25_7, frcp_a(c7), 1.0f));
}

__device__ __forceinline__ float srgb_lookup(const float* __restrict__ tab, float c) {
    int idx = __float2int_rz(c * (float)SRGB_N);
    idx = min(max(idx, 0), SRGB_N - 1);
    return tab[idx];
}

__device__ __forceinline__ float labf_lookup(const float* __restrict__ tab, float t) {
    int idx = (int)(__float_as_uint(t) - LABF_BASE) >> 13;
    idx = max(idx, 0);                         // t <= ~1.0002 so idx < LABF_N always
    float cb  = tab[idx];
    float lin = fmaf(7.787f, t, 0.13793103448f);
    return (t > 0.008856f) ? cb : lin;
}

__device__ __forceinline__ void rgb2lab(const float* __restrict__ stab,
                                        const float* __restrict__ ftab,
                                        float r, float g, float b,
                                        float& L, float& A, float& Bo) {
    float lr = srgb_lookup(stab, r);
    float lg = srgb_lookup(stab, g);
    float lb = srgb_lookup(stab, b);
    float xn = (0.4124564f / 0.95047f) * lr + (0.3575761f / 0.95047f) * lg + (0.1804375f / 0.95047f) * lb;
    float yn = 0.2126729f * lr + 0.7151522f * lg + 0.072175f * lb;
    float zn = (0.0193339f / 1.08883f) * lr + (0.119192f / 1.08883f) * lg + (0.9503041f / 1.08883f) * lb;
    float fx = labf_lookup(ftab, xn);
    float fy = labf_lookup(ftab, yn);
    float fz = labf_lookup(ftab, zn);
    L  = 116.0f * fy - 16.0f;
    A  = 500.0f * (fx - fy);
    Bo = 200.0f * (fy - fz);
}

// Fast atan2: deg-9 odd minimax poly + quadrant fixup. ~2e-6 rad err.
__device__ __forceinline__ float fast_atan2(float y, float x) {
    float ax = fabsf(x), ay = fabsf(y);
    float mx = fmaxf(ax, ay), mn = fminf(ax, ay);
    float t = mn * frcp_a(fmaxf(mx, 1e-38f));
    float t2 = t * t;
    float p = fmaf(t2, -0.01172120f, 0.05265332f);
    p = fmaf(t2, p, -0.11643287f);
    p = fmaf(t2, p, 0.19354346f);
    p = fmaf(t2, p, -0.33262347f);
    p = fmaf(t2, p, 0.99997726f);
    float r = p * t;
    if (ay > ax)   r = 1.5707963267948966f - r;
    if (x < 0.0f)  r = 3.1415926535897932f - r;
    return copysignf(r, y);
}

__device__ __forceinline__ float delta_e_2000(float L1, float a1, float b1,
                                              float L2, float a2, float b2) {
    const float PI_F     = 3.14159265358979323846f;
    const float TWO_PI_F = 6.28318530717958647692f;

    float C1 = fsqrt_a(fmaf(a1, a1, b1 * b1));
    float C2 = fsqrt_a(fmaf(a2, a2, b2 * b2));
    float Cavg = 0.5f * (C1 + C2);
    float G = 0.5f * (1.0f - chroma_ratio_sqrt(pow7(Cavg)));
    float a1p = a1 * (1.0f + G);
    float a2p = a2 * (1.0f + G);
    float C1p2 = fmaf(a1p, a1p, b1 * b1);
    float C2p2 = fmaf(a2p, a2p, b2 * b2);
    float C1p = fsqrt_a(C1p2);
    float C2p = fsqrt_a(C2p2);
    float h1p = fast_atan2(b1, a1p); if (h1p < 0.0f) h1p += TWO_PI_F;
    float h2p = fast_atan2(b2, a2p); if (h2p < 0.0f) h2p += TWO_PI_F;

    float dL = L2 - L1;
    float dC = C2p - C1p;

    // dH = 2*sqrt(C1p*C2p)*sin(dh/2) = sign(sin dh)*sqrt(2*(C1p*C2p - dot))
    float dot   = fmaf(a1p, a2p, b1 * b2);
    float cross = fmaf(b2, a1p, -b1 * a2p);
    float CC    = C1p * C2p;
    float dHmag = fsqrt_a(fmaxf(2.0f * (CC - dot), 0.0f));
    float dH = copysignf(dHmag, cross);

    float Lavg = 0.5f * (L1 + L2);
    float Cpavg = 0.5f * (C1p + C2p);
    float hsum = h1p + h2p;
    float havg = (fabsf(h1p - h2p) > PI_F) ? 0.5f * (hsum + TWO_PI_F) : 0.5f * hsum;

    // T via angle-addition from one sincos
    float sh, ch;
    __sincosf(havg, &sh, &ch);
    float c2 = fmaf(2.0f * ch, ch, -1.0f);
    float s2 = 2.0f * sh * ch;
    float c3 = c2 * ch - s2 * sh;
    float s3 = s2 * ch + c2 * sh;
    float c4 = fmaf(2.0f * c2, c2, -1.0f);
    float s4 = 2.0f * s2 * c2;
    const float C_P6   = 0.86602540378443865f, S_P6   = 0.5f;
    const float C_P30  = 0.99452189536827329f, S_P30  = 0.10452846326765347f;
    const float C_7P20 = 0.45399049973954680f, S_7P20 = 0.89100652418836786f;
    float T = 1.0f
            - 0.17f * fmaf(ch, C_P6, sh * S_P6)
            + 0.24f * c2
            + 0.32f * fmaf(c3, C_P30, -s3 * S_P30)
            - 0.20f * fmaf(c4, C_7P20, s4 * S_7P20);

    float hdeg = havg * (180.0f / PI_F);
    float u = (hdeg - 275.0f) * (1.0f / 25.0f);
    float theta = 30.0f * __expf(-u * u);

    float RC = 2.0f * chroma_ratio_sqrt(pow7(Cpavg));
    float x2t = 2.0f * theta;
    float k = rintf(x2t * 0.15915494309189535f);
    float xr = fmaf(-k, 6.2831855f, x2t);
    xr = fmaf(-k, -1.7484555e-7f, xr);
    float RT = -__sinf(xr) * RC;

    float Lm = Lavg - 50.0f;
    float Lm2 = Lm * Lm;
    float SL = fmaf(0.015f * Lm2, rsqrtf(20.0f + Lm2), 1.0f);
    float SC = fmaf(0.045f, Cpavg, 1.0f);
    float SH = fmaf(0.015f, Cpavg * T, 1.0f);

    // merged divides: one rcp
    float pSCSH = SC * SH;
    float pSLSH = SL * SH;
    float pSLSC = SL * SC;
    float D = frcp_a(pSLSC * SH);
    float xx = dL * (pSCSH * D);
    float yy = dC * (pSLSH * D);
    float zz = dH * (pSLSC * D);
    return fsqrt_a(fmaf(xx, xx, fmaf(yy, yy, fmaf(zz, zz, RT * yy * zz))));
}

__device__ __forceinline__ float row_loss(const float* __restrict__ stab,
                                          const float* __restrict__ ftab,
                                          float pr, float pg, float pb,
                                          float tr, float tg, float tb) {
    float d0 = pr - tr, d1 = pg - tg, d2 = pb - tb;
    float mse = (fmaf(d0, d0, fmaf(d1, d1, d2 * d2))) * (1.0f / 3.0f);
    float L1, A1, B1, L2, A2, B2;
    rgb2lab(stab, ftab, pr, pg, pb, L1, A1, B1);
    rgb2lab(stab, ftab, tr, tg, tb, L2, A2, B2);
    float de = delta_e_2000(L1, A1, B1, L2, A2, B2);
    return fmaf(0.2f, mse, 0.8f * de);
}

__global__ void __launch_bounds__(THREADS)
de_loss_kernel(const float* __restrict__ pred, const float* __restrict__ targ,
               float* __restrict__ out, int n, float inv_n) {
    __shared__ float s_srgb[SRGB_N];
    __shared__ float s_labf[LABF_N];

    // copy tables to shared (float4 strided)
    {
        const float4* gs = reinterpret_cast<const float4*>(g_srgb_tab);
        float4* ss = reinterpret_cast<float4*>(s_srgb);
        for (int i = threadIdx.x; i < SRGB_N / 4; i += THREADS) ss[i] = gs[i];
        const float4* gf = reinterpret_cast<const float4*>(g_labf_tab);
        float4* sf = reinterpret_cast<float4*>(s_labf);
        for (int i = threadIdx.x; i < LABF_N / 4; i += THREADS) sf[i] = gf[i];
    }
    __syncthreads();

    const int P = gridDim.x * blockDim.x;
    const int tid = blockIdx.x * blockDim.x + threadIdx.x;
    float acc = 0.0f;

    for (int base = tid * 4; base + 3 < n; base += P * 4) {
        const float4* p4 = reinterpret_cast<const float4*>(pred + (size_t)base * 3);
        const float4* t4 = reinterpret_cast<const float4*>(targ + (size_t)base * 3);
        float4 p0 = p4[0], p1 = p4[1], p2 = p4[2];
        float4 q0 = t4[0], q1 = t4[1], q2 = t4[2];

        acc += row_loss(s_srgb, s_labf, p0.x, p0.y, p0.z,  q0.x, q0.y, q0.z);
        acc += row_loss(s_srgb, s_labf, p0.w, p1.x, p1.y,  q0.w, q1.x, q1.y);
        acc += row_loss(s_srgb, s_labf, p1.z, p1.w, p2.x,  q1.z, q1.w, q2.x);
        acc += row_loss(s_srgb, s_labf, p2.y, p2.z, p2.w,  q2.y, q2.z, q2.w);
    }
    int tail_start = (n / (P * 4)) * (P * 4);
    for (int i = tail_start + tid; i < n; i += P) {
        const float* p = pred + (size_t)i * 3;
        const float* t = targ + (size_t)i * 3;
        acc += row_loss(s_srgb, s_labf, p[0], p[1], p[2], t[0], t[1], t[2]);
    }

    float v = warp_reduce(acc);
    __shared__ float sh[THREADS / 32];
    int lane = threadIdx.x & 31;
    int wid = threadIdx.x >> 5;
    if (lane == 0) sh[wid] = v;
    __syncthreads();
    if (wid == 0) {
        v = (lane < THREADS / 32) ? sh[lane] : 0.0f;
        v = warp_reduce(v);
        if (lane == 0) g_partials[blockIdx.x] = v;
    }

    __shared__ bool is_last;
    __threadfence();
    if (threadIdx.x == 0) {
        unsigned int c = atomicAdd(&g_count, 1u);
        is_last = (c == gridDim.x - 1);
    }
    __syncthreads();
    if (is_last) {
        float a = 0.0f;
        for (int i = threadIdx.x; i < BLOCKS; i += THREADS) a += g_partials[i];
        float w = warp_reduce(a);
        if (lane == 0) sh[wid] = w;
        __syncthreads();
        if (wid == 0) {
            w = (lane < THREADS / 32) ? sh[lane] : 0.0f;
            w = warp_reduce(w);
            if (lane == 0) {
                out[0] = w * inv_n;
                g_count = 0;
            }
        }
    }
}

extern "C" void kernel_launch(void* const* d_in, const int* in_sizes, int n_in,
                              void* d_out, int out_size) {
    const float* pred = (const float*)d_in[0];
    const float* targ = (const float*)d_in[1];
    int n = in_sizes[0] / 3;
    init_tables_kernel<<<(LABF_N + 255) / 256, 256>>>();
    de_loss_kernel<<<BLOCKS, THREADS>>>(pred, targ, (float*)d_out, n, 1.0f / (float)n);
}

// round 5
// speedup vs baseline: 1.4373x; 1.0613x over previous
#include <cuda_runtime.h>
#include <math.h>

// ---------------------------------------------------------------------------
// DeltaE2000 + MSE loss over 16.7M rgb pairs.
// R5: one atan2 (circular-mean havg), cos/sin(havg) from vector normalize,
// RT=sin(60*exp(-u^2)) via shared table, smaller labf table, 6 blocks/SM.
// ---------------------------------------------------------------------------

constexpr int THREADS = 256;
constexpr int BLOCKS  = 4096;
constexpr int SRGB_N  = 2048;
constexpr int LABF_N  = 4096;                 // 8 octaves [2^-7, 2), 512/octave
constexpr unsigned LABF_BASE = 0x3C000000u;   // bits of 2^-7
constexpr int RTF_N   = 2048;                 // sin(2*theta) vs hdeg on [187.5, 362.5]
constexpr float RTF_LO = 187.5f;
constexpr float RTF_SPAN = 175.0f;

__device__ float g_partials[BLOCKS];
__device__ unsigned int g_count = 0;
__device__ float g_srgb_tab[SRGB_N];
__device__ float g_labf_tab[LABF_N];
__device__ float g_rtf_tab[RTF_N];

__global__ void init_tables_kernel() {
    int i = blockIdx.x * blockDim.x + threadIdx.x;
    if (i < SRGB_N) {
        float c = (i + 0.5f) / (float)SRGB_N;
        float hi = powf((c + 0.055f) / 1.055f, 2.4f);
        float lo = c / 12.92f;
        g_srgb_tab[i] = (c > 0.04045f) ? hi : lo;
    }
    if (i < LABF_N) {
        unsigned bits = LABF_BASE + ((unsigned)i << 14) + (1u << 13); // bucket center
        g_labf_tab[i] = cbrtf(__uint_as_float(bits));
    }
    if (i < RTF_N) {
        double d = (double)RTF_LO + (i + 0.5) * ((double)RTF_SPAN / RTF_N);
        double u = (d - 275.0) / 25.0;
        g_rtf_tab[i] = (float)sin(60.0 * exp(-u * u));
    }
}

__device__ __forceinline__ float warp_reduce(float v) {
#pragma unroll
    for (int o = 16; o > 0; o >>= 1) v += __shfl_down_sync(0xffffffffu, v, o);
    return v;
}

__device__ __forceinline__ float fsqrt_a(float x) {
    float r; asm("sqrt.approx.f32 %0, %1;" : "=f"(r) : "f"(x)); return r;
}
__device__ __forceinline__ float frcp_a(float x) {
    float r; asm("rcp.approx.f32 %0, %1;" : "=f"(r) : "f"(x)); return r;
}

__device__ __forceinline__ float pow7(float x) {
    float x2 = x * x;
    float x4 = x2 * x2;
    return x4 * x2 * x;
}

// sqrt(c7/(c7+P)) = rsqrt(1 + P/c7); c7=0 -> rcp=inf -> rsqrt(inf)=0 (correct)
__device__ __forceinline__ float chroma_ratio_sqrt(float c7) {
    const float POW25_7 = 6103515625.0f;
    return rsqrtf(fmaf(POW25_7, frcp_a(c7), 1.0f));
}

__device__ __forceinline__ float srgb_lookup(const float* __restrict__ tab, float c) {
    int idx = __float2int_rz(c * (float)SRGB_N);   // c in [0,1) -> idx in [0,2047]
    return tab[idx];
}

__device__ __forceinline__ float labf_lookup(const float* __restrict__ tab, float t) {
    int idx = (int)(__float_as_uint(t) - LABF_BASE) >> 14;
    idx = max(idx, 0);                              // tiny t -> linear branch anyway
    float cb  = tab[idx];
    float lin = fmaf(7.787f, t, 0.13793103448f);
    return (t > 0.008856f) ? cb : lin;
}

__device__ __forceinline__ void rgb2lab(const float* __restrict__ stab,
                                        const float* __restrict__ ftab,
                                        float r, float g, float b,
                                        float& L, float& A, float& Bo) {
    float lr = srgb_lookup(stab, r);
    float lg = srgb_lookup(stab, g);
    float lb = srgb_lookup(stab, b);
    float xn = (0.4124564f / 0.95047f) * lr + (0.3575761f / 0.95047f) * lg + (0.1804375f / 0.95047f) * lb;
    float yn = 0.2126729f * lr + 0.7151522f * lg + 0.072175f * lb;
    float zn = (0.0193339f / 1.08883f) * lr + (0.119192f / 1.08883f) * lg + (0.9503041f / 1.08883f) * lb;
    float fx = labf_lookup(ftab, xn);
    float fy = labf_lookup(ftab, yn);
    float fz = labf_lookup(ftab, zn);
    L  = 116.0f * fy - 16.0f;
    A  = 500.0f * (fx - fy);
    Bo = 200.0f * (fy - fz);
}

// Fast atan2: deg-9 odd minimax poly + quadrant fixup. ~2e-6 rad err.
__device__ __forceinline__ float fast_atan2(float y, float x) {
    float ax = fabsf(x), ay = fabsf(y);
    float mx = fmaxf(ax, ay), mn = fminf(ax, ay);
    float t = mn * frcp_a(fmaxf(mx, 1e-38f));
    float t2 = t * t;
    float p = fmaf(t2, -0.01172120f, 0.05265332f);
    p = fmaf(t2, p, -0.11643287f);
    p = fmaf(t2, p, 0.19354346f);
    p = fmaf(t2, p, -0.33262347f);
    p = fmaf(t2, p, 0.99997726f);
    float r = p * t;
    if (ay > ax)   r = 1.5707963267948966f - r;
    if (x < 0.0f)  r = 3.1415926535897932f - r;
    return copysignf(r, y);
}

__device__ __forceinline__ float delta_e_2000(const float* __restrict__ rtab,
                                              float L1, float a1, float b1,
                                              float L2, float a2, float b2) {
    float C1 = fsqrt_a(fmaf(a1, a1, b1 * b1));
    float C2 = fsqrt_a(fmaf(a2, a2, b2 * b2));
    float Cavg = 0.5f * (C1 + C2);
    float G = 0.5f * (1.0f - chroma_ratio_sqrt(pow7(Cavg)));
    float a1p = a1 * (1.0f + G);
    float a2p = a2 * (1.0f + G);
    float C1p = fsqrt_a(fmaf(a1p, a1p, b1 * b1));
    float C2p = fsqrt_a(fmaf(a2p, a2p, b2 * b2));

    float dL = L2 - L1;
    float dC = C2p - C1p;

    // dH = sign(sin dh) * sqrt(2*(C1p*C2p - dot))
    float dot   = fmaf(a1p, a2p, b1 * b2);
    float cross = fmaf(b2, a1p, -b1 * a2p);
    float CC    = C1p * C2p;
    float dHmag = fsqrt_a(fmaxf(2.0f * (CC - dot), 0.0f));
    float dH = copysignf(dHmag, cross);

    // Circular-mean bisector: angle of (sx, sy) == havg (mod 2pi).
    float sx = fmaf(a1p, C2p, a2p * C1p);
    float sy = fmaf(b1,  C2p, b2  * C1p);
    float rs = rsqrtf(fmaxf(fmaf(sx, sx, sy * sy), 1e-30f));
    float ch = sx * rs;
    float sh = sy * rs;

    // T via angle-addition from (ch, sh)
    float c2 = fmaf(2.0f * ch, ch, -1.0f);
    float s2 = 2.0f * sh * ch;
    float c3 = c2 * ch - s2 * sh;
    float s3 = s2 * ch + c2 * sh;
    float c4 = fmaf(2.0f * c2, c2, -1.0f);
    float s4 = 2.0f * s2 * c2;
    const float C_P6   = 0.86602540378443865f, S_P6   = 0.5f;
    const float C_P30  = 0.99452189536827329f, S_P30  = 0.10452846326765347f;
    const float C_7P20 = 0.45399049973954680f, S_7P20 = 0.89100652418836786f;
    float T = 1.0f
            - 0.17f * fmaf(ch, C_P6, sh * S_P6)
            + 0.24f * c2
            + 0.32f * fmaf(c3, C_P30, -s3 * S_P30)
            - 0.20f * fmaf(c4, C_7P20, s4 * S_7P20);

    // hdeg in [0, 360)
    float havg0 = fast_atan2(sy, sx);
    float hdeg = havg0 * 57.295779513082321f;
    if (hdeg < 0.0f) hdeg += 360.0f;

    // RT = -sin(2*theta) * RC via table (nonzero only on [187.5, 362.5])
    float fi = (hdeg - RTF_LO) * ((float)RTF_N / RTF_SPAN);
    int ridx = __float2int_rz(fi);
    float rtf = (fi >= 0.0f && ridx < RTF_N) ? rtab[ridx] : 0.0f;

    float Cpavg = 0.5f * (C1p + C2p);
    float RC = 2.0f * chroma_ratio_sqrt(pow7(Cpavg));
    float RT = -rtf * RC;

    float Lavg = 0.5f * (L1 + L2);
    float Lm = Lavg - 50.0f;
    float Lm2 = Lm * Lm;
    float SL = fmaf(0.015f * Lm2, rsqrtf(20.0f + Lm2), 1.0f);
    float SC = fmaf(0.045f, Cpavg, 1.0f);
    float SH = fmaf(0.015f, Cpavg * T, 1.0f);

    // merged divides: one rcp
    float pSCSH = SC * SH;
    float pSLSH = SL * SH;
    float pSLSC = SL * SC;
    float D = frcp_a(pSLSC * SH);
    float xx = dL * (pSCSH * D);
    float yy = dC * (pSLSH * D);
    float zz = dH * (pSLSC * D);
    return fsqrt_a(fmaf(xx, xx, fmaf(yy, yy, fmaf(zz, zz, RT * yy * zz))));
}

__device__ __forceinline__ float row_loss(const float* __restrict__ stab,
                                          const float* __restrict__ ftab,
                                          const float* __restrict__ rtab,
                                          float pr, float pg, float pb,
                                          float tr, float tg, float tb) {
    float d0 = pr - tr, d1 = pg - tg, d2 = pb - tb;
    float mse = (fmaf(d0, d0, fmaf(d1, d1, d2 * d2))) * (1.0f / 3.0f);
    float L1, A1, B1, L2, A2, B2;
    rgb2lab(stab, ftab, pr, pg, pb, L1, A1, B1);
    rgb2lab(stab, ftab, tr, tg, tb, L2, A2, B2);
    float de = delta_e_2000(rtab, L1, A1, B1, L2, A2, B2);
    return fmaf(0.2f, mse, 0.8f * de);
}

__global__ void __launch_bounds__(THREADS, 6)
de_loss_kernel(const float* __restrict__ pred, const float* __restrict__ targ,
               float* __restrict__ out, int n, float inv_n) {
    __shared__ float s_srgb[SRGB_N];
    __shared__ float s_labf[LABF_N];
    __shared__ float s_rtf[RTF_N];

    {
        const float4* gs = reinterpret_cast<const float4*>(g_srgb_tab);
        float4* ss = reinterpret_cast<float4*>(s_srgb);
        for (int i = threadIdx.x; i < SRGB_N / 4; i += THREADS) ss[i] = gs[i];
        const float4* gf = reinterpret_cast<const float4*>(g_labf_tab);
        float4* sf = reinterpret_cast<float4*>(s_labf);
        for (int i = threadIdx.x; i < LABF_N / 4; i += THREADS) sf[i] = gf[i];
        const float4* gr = reinterpret_cast<const float4*>(g_rtf_tab);
        float4* sr = reinterpret_cast<float4*>(s_rtf);
        for (int i = threadIdx.x; i < RTF_N / 4; i += THREADS) sr[i] = gr[i];
    }
    __syncthreads();

    const int P = gridDim.x * blockDim.x;
    const int tid = blockIdx.x * blockDim.x + threadIdx.x;
    float acc = 0.0f;

    for (int base = tid * 4; base + 3 < n; base += P * 4) {
        const float4* p4 = reinterpret_cast<const float4*>(pred + (size_t)base * 3);
        const float4* t4 = reinterpret_cast<const float4*>(targ + (size_t)base * 3);
        float4 p0 = p4[0], p1 = p4[1], p2 = p4[2];
        float4 q0 = t4[0], q1 = t4[1], q2 = t4[2];

        acc += row_loss(s_srgb, s_labf, s_rtf, p0.x, p0.y, p0.z,  q0.x, q0.y, q0.z);
        acc += row_loss(s_srgb, s_labf, s_rtf, p0.w, p1.x, p1.y,  q0.w, q1.x, q1.y);
        acc += row_loss(s_srgb, s_labf, s_rtf, p1.z, p1.w, p2.x,  q1.z, q1.w, q2.x);
        acc += row_loss(s_srgb, s_labf, s_rtf, p2.y, p2.z, p2.w,  q2.y, q2.z, q2.w);
    }
    int tail_start = (n / (P * 4)) * (P * 4);
    for (int i = tail_start + tid; i < n; i += P) {
        const float* p = pred + (size_t)i * 3;
        const float* t = targ + (size_t)i * 3;
        acc += row_loss(s_srgb, s_labf, s_rtf, p[0], p[1], p[2], t[0], t[1], t[2]);
    }

    float v = warp_reduce(acc);
    __shared__ float sh[THREADS / 32];
    int lane = threadIdx.x & 31;
    int wid = threadIdx.x >> 5;
    if (lane == 0) sh[wid] = v;
    __syncthreads();
    if (wid == 0) {
        v = (lane < THREADS / 32) ? sh[lane] : 0.0f;
        v = warp_reduce(v);
        if (lane == 0) g_partials[blockIdx.x] = v;
    }

    __shared__ bool is_last;
    __threadfence();
    if (threadIdx.x == 0) {
        unsigned int c = atomicAdd(&g_count, 1u);
        is_last = (c == gridDim.x - 1);
    }
    __syncthreads();
    if (is_last) {
        float a = 0.0f;
        for (int i = threadIdx.x; i < BLOCKS; i += THREADS) a += g_partials[i];
        float w = warp_reduce(a);
        if (lane == 0) sh[wid] = w;
        __syncthreads();
        if (wid == 0) {
            w = (lane < THREADS / 32) ? sh[lane] : 0.0f;
            w = warp_reduce(w);
            if (lane == 0) {
                out[0] = w * inv_n;
                g_count = 0;
            }
        }
    }
}

extern "C" void kernel_launch(void* const* d_in, const int* in_sizes, int n_in,
                              void* d_out, int out_size) {
    const float* pred = (const float*)d_in[0];
    const float* targ = (const float*)d_in[1];
    int n = in_sizes[0] / 3;
    init_tables_kernel<<<(LABF_N + 255) / 256, 256>>>();
    de_loss_kernel<<<BLOCKS, THREADS>>>(pred, targ, (float*)d_out, n, 1.0f / (float)n);
}

// round 6
// speedup vs baseline: 1.4927x; 1.0385x over previous
#include <cuda_runtime.h>
#include <math.h>

// ---------------------------------------------------------------------------
// DeltaE2000 + MSE loss over 16.7M rgb pairs. Issue-bound.
// R6: hue section replaced by octant-indexed float2 table {T(h), sin(2theta(h))}
//     (kills atan2 poly, angle-addition trig, hdeg wrap, normalize);
//     branch-free labf table (linear region baked in).
// ---------------------------------------------------------------------------

constexpr int THREADS = 256;
constexpr int BLOCKS  = 4096;

constexpr int SRGB_N  = 2048;
constexpr int LABF_N  = 2304;                 // 18 octaves [2^-17, 2), 128/octave
constexpr unsigned LABF_BASE = 0x37000000u;   // bits of 2^-17
constexpr int HT_N    = 2048;                 // 8 octants x 256 t-bins

__device__ float g_partials[BLOCKS];
__device__ unsigned int g_count = 0;
__device__ float  g_srgb_tab[SRGB_N];
__device__ float  g_labf_tab[LABF_N];
__device__ float2 g_ht_tab[HT_N];

__global__ void init_tables_kernel() {
    int i = blockIdx.x * blockDim.x + threadIdx.x;
    if (i < SRGB_N) {
        float c = (i + 0.5f) / (float)SRGB_N;
        float hi = powf((c + 0.055f) / 1.055f, 2.4f);
        float lo = c / 12.92f;
        g_srgb_tab[i] = (c > 0.04045f) ? hi : lo;
    }
    if (i < LABF_N) {
        unsigned bits = LABF_BASE + ((unsigned)i << 16) + (1u << 15); // bucket center
        double t = (double)__uint_as_float(bits);
        double f = (t > 0.008856) ? cbrt(t) : 7.787 * t + 16.0 / 116.0;
        g_labf_tab[i] = (float)f;
    }
    if (i < HT_N) {
        const double PI = 3.14159265358979323846;
        int tbin = i & 255;
        int swp  = (i >> 8)  & 1;
        int xng  = (i >> 9)  & 1;
        int yng  = (i >> 10) & 1;
        double t = (tbin + 0.5) / 256.0;
        double a = atan(t);
        double phi = swp ? (PI / 2.0 - a) : a;
        if (xng) phi = PI - phi;
        if (yng) phi = -phi;
        if (phi < 0.0) phi += 2.0 * PI;       // havg in [0, 2pi)
        double T = 1.0
                 - 0.17 * cos(phi - PI / 6.0)
                 + 0.24 * cos(2.0 * phi)
                 + 0.32 * cos(3.0 * phi + PI / 30.0)
                 - 0.20 * cos(4.0 * phi - 7.0 * PI / 20.0);
        double hdeg = phi * 180.0 / PI;
        double u = (hdeg - 275.0) / 25.0;
        double s2t = sin(60.0 * exp(-u * u)); // sin(2*theta)
        g_ht_tab[i] = make_float2((float)T, (float)s2t);
    }
}

__device__ __forceinline__ float warp_reduce(float v) {
#pragma unroll
    for (int o = 16; o > 0; o >>= 1) v += __shfl_down_sync(0xffffffffu, v, o);
    return v;
}

__device__ __forceinline__ float fsqrt_a(float x) {
    float r; asm("sqrt.approx.f32 %0, %1;" : "=f"(r) : "f"(x)); return r;
}
__device__ __forceinline__ float frcp_a(float x) {
    float r; asm("rcp.approx.f32 %0, %1;" : "=f"(r) : "f"(x)); return r;
}

__device__ __forceinline__ float pow7(float x) {
    float x2 = x * x;
    float x4 = x2 * x2;
    return x4 * x2 * x;
}

// sqrt(c7/(c7+P)) = rsqrt(1 + P/c7); c7=0 -> rcp=inf -> rsqrt(inf)=0 (correct)
__device__ __forceinline__ float chroma_ratio_sqrt(float c7) {
    const float POW25_7 = 6103515625.0f;
    return rsqrtf(fmaf(POW25_7, frcp_a(c7), 1.0f));
}

__device__ __forceinline__ float srgb_lookup(const float* __restrict__ tab, float c) {
    int idx = __float2int_rz(c * (float)SRGB_N);   // c in [0,1)
    return tab[idx];
}

// Branch-free: table covers [2^-17, 2); linear region baked into entries.
__device__ __forceinline__ float labf_lookup(const float* __restrict__ tab, float t) {
    int idx = (int)(__float_as_uint(t) - LABF_BASE) >> 16;
    idx = max(idx, 0);                              // t in [0, ~1.0002) -> idx < LABF_N
    return tab[idx];
}

__device__ __forceinline__ void rgb2lab(const float* __restrict__ stab,
                                        const float* __restrict__ ftab,
                                        float r, float g, float b,
                                        float& L, float& A, float& Bo) {
    float lr = srgb_lookup(stab, r);
    float lg = srgb_lookup(stab, g);
    float lb = srgb_lookup(stab, b);
    float xn = (0.4124564f / 0.95047f) * lr + (0.3575761f / 0.95047f) * lg + (0.1804375f / 0.95047f) * lb;
    float yn = 0.2126729f * lr + 0.7151522f * lg + 0.072175f * lb;
    float zn = (0.0193339f / 1.08883f) * lr + (0.119192f / 1.08883f) * lg + (0.9503041f / 1.08883f) * lb;
    float fx = labf_lookup(ftab, xn);
    float fy = labf_lookup(ftab, yn);
    float fz = labf_lookup(ftab, zn);
    L  = 116.0f * fy - 16.0f;
    A  = 500.0f * (fx - fy);
    Bo = 200.0f * (fy - fz);
}

__device__ __forceinline__ float delta_e_2000(const float2* __restrict__ httab,
                                              float L1, float a1, float b1,
                                              float L2, float a2, float b2) {
    float C1 = fsqrt_a(fmaf(a1, a1, b1 * b1));
    float C2 = fsqrt_a(fmaf(a2, a2, b2 * b2));
    float Cavg = 0.5f * (C1 + C2);
    float G = 0.5f * (1.0f - chroma_ratio_sqrt(pow7(Cavg)));
    float a1p = a1 * (1.0f + G);
    float a2p = a2 * (1.0f + G);
    float C1p = fsqrt_a(fmaf(a1p, a1p, b1 * b1));
    float C2p = fsqrt_a(fmaf(a2p, a2p, b2 * b2));

    float dL = L2 - L1;
    float dC = C2p - C1p;

    // dH = sign(sin dh) * sqrt(2*(C1p*C2p - dot))
    float dot   = fmaf(a1p, a2p, b1 * b2);
    float cross = fmaf(b2, a1p, -b1 * a2p);
    float CC    = C1p * C2p;
    float dHmag = fsqrt_a(fmaxf(2.0f * (CC - dot), 0.0f));
    float dH = copysignf(dHmag, cross);

    // Circular-mean bisector direction (angle == havg mod 2pi)
    float sx = fmaf(a1p, C2p, a2p * C1p);
    float sy = fmaf(b1,  C2p, b2  * C1p);

    // Octant-indexed lookup of {T(havg), sin(2*theta(havg))}
    float ax = fabsf(sx), ay = fabsf(sy);
    float mx = fmaxf(ax, ay), mn = fminf(ax, ay);
    float t = mn * frcp_a(fmaxf(mx, 1e-38f));
    int idx = min(__float2int_rz(t * 256.0f), 255);
    if (ay > ax)    idx |= 256;
    if (sx < 0.0f)  idx |= 512;
    if (sy < 0.0f)  idx |= 1024;
    float2 ht = httab[idx];
    float T   = ht.x;
    float rtf = ht.y;

    float Cpavg = 0.5f * (C1p + C2p);
    float RC = 2.0f * chroma_ratio_sqrt(pow7(Cpavg));
    float RT = -rtf * RC;

    float Lavg = 0.5f * (L1 + L2);
    float Lm = Lavg - 50.0f;
    float Lm2 = Lm * Lm;
    float SL = fmaf(0.015f * Lm2, rsqrtf(20.0f + Lm2), 1.0f);
    float SC = fmaf(0.045f, Cpavg, 1.0f);
    float SH = fmaf(0.015f, Cpavg * T, 1.0f);

    // merged divides: one rcp
    float pSCSH = SC * SH;
    float pSLSH = SL * SH;
    float pSLSC = SL * SC;
    float D = frcp_a(pSLSC * SH);
    float xx = dL * (pSCSH * D);
    float yy = dC * (pSLSH * D);
    float zz = dH * (pSLSC * D);
    return fsqrt_a(fmaf(xx, xx, fmaf(yy, yy, fmaf(zz, zz, RT * yy * zz))));
}

__device__ __forceinline__ float row_loss(const float* __restrict__ stab,
                                          const float* __restrict__ ftab,
                                          const float2* __restrict__ httab,
                                          float pr, float pg, float pb,
                                          float tr, float tg, float tb) {
    float d0 = pr - tr, d1 = pg - tg, d2 = pb - tb;
    float mse = (fmaf(d0, d0, fmaf(d1, d1, d2 * d2))) * (1.0f / 3.0f);
    float L1, A1, B1, L2, A2, B2;
    rgb2lab(stab, ftab, pr, pg, pb, L1, A1, B1);
    rgb2lab(stab, ftab, tr, tg, tb, L2, A2, B2);
    float de = delta_e_2000(httab, L1, A1, B1, L2, A2, B2);
    return fmaf(0.2f, mse, 0.8f * de);
}

__global__ void __launch_bounds__(THREADS, 6)
de_loss_kernel(const float* __restrict__ pred, const float* __restrict__ targ,
               float* __restrict__ out, int n, float inv_n) {
    __shared__ float  s_srgb[SRGB_N];
    __shared__ float  s_labf[LABF_N];
    __shared__ float2 s_ht[HT_N];

    {
        const float4* gs = reinterpret_cast<const float4*>(g_srgb_tab);
        float4* ss = reinterpret_cast<float4*>(s_srgb);
        for (int i = threadIdx.x; i < SRGB_N / 4; i += THREADS) ss[i] = gs[i];
        const float4* gf = reinterpret_cast<const float4*>(g_labf_tab);
        float4* sf = reinterpret_cast<float4*>(s_labf);
        for (int i = threadIdx.x; i < LABF_N / 4; i += THREADS) sf[i] = gf[i];
        const float4* gh = reinterpret_cast<const float4*>(g_ht_tab);
        float4* shh = reinterpret_cast<float4*>(s_ht);
        for (int i = threadIdx.x; i < HT_N / 2; i += THREADS) shh[i] = gh[i];
    }
    __syncthreads();

    const int P = gridDim.x * blockDim.x;
    const int tid = blockIdx.x * blockDim.x + threadIdx.x;
    float acc = 0.0f;

    for (int base = tid * 4; base + 3 < n; base += P * 4) {
        const float4* p4 = reinterpret_cast<const float4*>(pred + (size_t)base * 3);
        const float4* t4 = reinterpret_cast<const float4*>(targ + (size_t)base * 3);
        float4 p0 = p4[0], p1 = p4[1], p2 = p4[2];
        float4 q0 = t4[0], q1 = t4[1], q2 = t4[2];

        acc += row_loss(s_srgb, s_labf, s_ht, p0.x, p0.y, p0.z,  q0.x, q0.y, q0.z);
        acc += row_loss(s_srgb, s_labf, s_ht, p0.w, p1.x, p1.y,  q0.w, q1.x, q1.y);
        acc += row_loss(s_srgb, s_labf, s_ht, p1.z, p1.w, p2.x,  q1.z, q1.w, q2.x);
        acc += row_loss(s_srgb, s_labf, s_ht, p2.y, p2.z, p2.w,  q2.y, q2.z, q2.w);
    }
    int tail_start = (n / (P * 4)) * (P * 4);
    for (int i = tail_start + tid; i < n; i += P) {
        const float* p = pred + (size_t)i * 3;
        const float* t = targ + (size_t)i * 3;
        acc += row_loss(s_srgb, s_labf, s_ht, p[0], p[1], p[2], t[0], t[1], t[2]);
    }

    float v = warp_reduce(acc);
    __shared__ float sh[THREADS / 32];
    int lane = threadIdx.x & 31;
    int wid = threadIdx.x >> 5;
    if (lane == 0) sh[wid] = v;
    __syncthreads();
    if (wid == 0) {
        v = (lane < THREADS / 32) ? sh[lane] : 0.0f;
        v = warp_reduce(v);
        if (lane == 0) g_partials[blockIdx.x] = v;
    }

    __shared__ bool is_last;
    __threadfence();
    if (threadIdx.x == 0) {
        unsigned int c = atomicAdd(&g_count, 1u);
        is_last = (c == gridDim.x - 1);
    }
    __syncthreads();
    if (is_last) {
        float a = 0.0f;
        for (int i = threadIdx.x; i < BLOCKS; i += THREADS) a += g_partials[i];
        float w = warp_reduce(a);
        if (lane == 0) sh[wid] = w;
        __syncthreads();
        if (wid == 0) {
            w = (lane < THREADS / 32) ? sh[lane] : 0.0f;
            w = warp_reduce(w);
            if (lane == 0) {
                out[0] = w * inv_n;
                g_count = 0;
            }
        }
    }
}

extern "C" void kernel_launch(void* const* d_in, const int* in_sizes, int n_in,
                              void* d_out, int out_size) {
    const float* pred = (const float*)d_in[0];
    const float* targ = (const float*)d_in[1];
    int n = in_sizes[0] / 3;
    init_tables_kernel<<<(LABF_N + 255) / 256, 256>>>();
    de_loss_kernel<<<BLOCKS, THREADS>>>(pred, targ, (float*)d_out, n, 1.0f / (float)n);
}

// round 7
// speedup vs baseline: 1.8167x; 1.2171x over previous
#include <cuda_runtime.h>
#include <cuda_fp16.h>
#include <math.h>

// ---------------------------------------------------------------------------
// DeltaE2000 + MSE loss over 16.7M rgb pairs. Issue+L1tex co-bound.
// R7: all-float table init (was fp64 -> 13us/replay), HT table as half2
//     (LDS.32 instead of LDS.64), micro instruction trims.
// ---------------------------------------------------------------------------

constexpr int THREADS = 256;
constexpr int BLOCKS  = 4096;

constexpr int SRGB_N  = 2048;
constexpr int LABF_N  = 2304;                 // 18 octaves [2^-17, 2), 128/octave
constexpr unsigned LABF_BASE = 0x37000000u;   // bits of 2^-17
constexpr int HT_N    = 2048;                 // 8 octants x 256 t-bins

__device__ float   g_partials[BLOCKS];
__device__ unsigned int g_count = 0;
__device__ float   g_srgb_tab[SRGB_N];
__device__ float   g_labf_tab[LABF_N];
__device__ __half2 g_ht_tab[HT_N];

__global__ void init_tables_kernel() {
    int i = blockIdx.x * blockDim.x + threadIdx.x;
    if (i < SRGB_N) {
        float c = (i + 0.5f) / (float)SRGB_N;
        float hi = powf((c + 0.055f) / 1.055f, 2.4f);
        float lo = c / 12.92f;
        g_srgb_tab[i] = (c > 0.04045f) ? hi : lo;
    }
    if (i < LABF_N) {
        unsigned bits = LABF_BASE + ((unsigned)i << 16) + (1u << 15); // bucket center
        float t = __uint_as_float(bits);
        float f = (t > 0.008856f) ? cbrtf(t) : fmaf(7.787f, t, 16.0f / 116.0f);
        g_labf_tab[i] = f;
    }
    if (i < HT_N) {
        const float PI = 3.14159265358979323846f;
        int tbin = i & 255;
        int swp  = (i >> 8)  & 1;
        int xng  = (i >> 9)  & 1;
        int yng  = (i >> 10) & 1;
        float t = (tbin + 0.5f) / 256.0f;
        float a = atanf(t);
        float phi = swp ? (PI / 2.0f - a) : a;
        if (xng) phi = PI - phi;
        if (yng) phi = -phi;
        if (phi < 0.0f) phi += 2.0f * PI;       // havg in [0, 2pi)
        float T = 1.0f
                - 0.17f * cosf(phi - PI / 6.0f)
                + 0.24f * cosf(2.0f * phi)
                + 0.32f * cosf(3.0f * phi + PI / 30.0f)
                - 0.20f * cosf(4.0f * phi - 7.0f * PI / 20.0f);
        float hdeg = phi * (180.0f / PI);
        float u = (hdeg - 275.0f) * (1.0f / 25.0f);
        float s2t = sinf(60.0f * expf(-u * u));  // sin(2*theta)
        g_ht_tab[i] = __floats2half2_rn(T, s2t);
    }
}

__device__ __forceinline__ float warp_reduce(float v) {
#pragma unroll
    for (int o = 16; o > 0; o >>= 1) v += __shfl_down_sync(0xffffffffu, v, o);
    return v;
}

__device__ __forceinline__ float fsqrt_a(float x) {
    float r; asm("sqrt.approx.f32 %0, %1;" : "=f"(r) : "f"(x)); return r;
}
__device__ __forceinline__ float frcp_a(float x) {
    float r; asm("rcp.approx.f32 %0, %1;" : "=f"(r) : "f"(x)); return r;
}

__device__ __forceinline__ float pow7(float x) {
    float x2 = x * x;
    float x4 = x2 * x2;
    return x4 * x2 * x;
}

// sqrt(c7/(c7+P)) = rsqrt(1 + P/c7); c7=0 -> rcp=inf -> rsqrt(inf)=0 (correct)
__device__ __forceinline__ float chroma_ratio_sqrt(float c7) {
    const float POW25_7 = 6103515625.0f;
    return rsqrtf(fmaf(POW25_7, frcp_a(c7), 1.0f));
}

__device__ __forceinline__ float srgb_lookup(const float* __restrict__ tab, float c) {
    int idx = __float2int_rz(c * (float)SRGB_N);   // c in [0,1)
    return tab[idx];
}

// Branch-free: table covers [2^-17, 2); linear region baked into entries.
__device__ __forceinline__ float labf_lookup(const float* __restrict__ tab, float t) {
    int idx = (int)(__float_as_uint(t) - LABF_BASE) >> 16;
    idx = max(idx, 0);
    return tab[idx];
}

__device__ __forceinline__ void rgb2lab(const float* __restrict__ stab,
                                        const float* __restrict__ ftab,
                                        float r, float g, float b,
                                        float& L, float& A, float& Bo) {
    float lr = srgb_lookup(stab, r);
    float lg = srgb_lookup(stab, g);
    float lb = srgb_lookup(stab, b);
    float xn = (0.4124564f / 0.95047f) * lr + (0.3575761f / 0.95047f) * lg + (0.1804375f / 0.95047f) * lb;
    float yn = 0.2126729f * lr + 0.7151522f * lg + 0.072175f * lb;
    float zn = (0.0193339f / 1.08883f) * lr + (0.119192f / 1.08883f) * lg + (0.9503041f / 1.08883f) * lb;
    float fx = labf_lookup(ftab, xn);
    float fy = labf_lookup(ftab, yn);
    float fz = labf_lookup(ftab, zn);
    L  = 116.0f * fy - 16.0f;
    A  = 500.0f * (fx - fy);
    Bo = 200.0f * (fy - fz);
}

__device__ __forceinline__ float delta_e_2000(const __half2* __restrict__ httab,
                                              float L1, float a1, float b1,
                                              float L2, float a2, float b2) {
    float C1 = fsqrt_a(fmaf(a1, a1, b1 * b1));
    float C2 = fsqrt_a(fmaf(a2, a2, b2 * b2));
    float Cavg = 0.5f * (C1 + C2);
    float ratioA = chroma_ratio_sqrt(pow7(Cavg));
    float g1 = fmaf(-0.5f, ratioA, 1.5f);      // 1 + G
    float a1p = a1 * g1;
    float a2p = a2 * g1;
    float C1p = fsqrt_a(fmaf(a1p, a1p, b1 * b1));
    float C2p = fsqrt_a(fmaf(a2p, a2p, b2 * b2));

    float dL = L2 - L1;
    float dC = C2p - C1p;

    // dH = sign(sin dh) * sqrt(2*(C1p*C2p - dot))
    float dot   = fmaf(a1p, a2p, b1 * b2);
    float cross = fmaf(b2, a1p, -b1 * a2p);
    float CC    = C1p * C2p;
    float dHmag = fsqrt_a(fmaxf(2.0f * (CC - dot), 0.0f));
    float dH = copysignf(dHmag, cross);

    // Circular-mean bisector direction (angle == havg mod 2pi)
    float sx = fmaf(a1p, C2p, a2p * C1p);
    float sy = fmaf(b1,  C2p, b2  * C1p);

    // Octant-indexed lookup of {T(havg), sin(2*theta(havg))} (half2)
    float ax = fabsf(sx), ay = fabsf(sy);
    float mx = fmaxf(ax, ay), mn = fminf(ax, ay);
    float t = mn * frcp_a(mx);                 // mx==0 -> NaN -> idx 0 (harmless: dH=0)
    int idx = min(__float2int_rz(t * 256.0f), 255);
    if (ay > ax)    idx |= 256;
    if (sx < 0.0f)  idx |= 512;
    if (sy < 0.0f)  idx |= 1024;
    float2 ht = __half22float2(httab[idx]);
    float T   = ht.x;
    float rtf = ht.y;

    float Cpavg = 0.5f * (C1p + C2p);
    float RT = -2.0f * rtf * chroma_ratio_sqrt(pow7(Cpavg));

    float Lavg = 0.5f * (L1 + L2);
    float Lm = Lavg - 50.0f;
    float Lm2 = Lm * Lm;
    float SL = fmaf(0.015f * Lm2, rsqrtf(20.0f + Lm2), 1.0f);
    float SC = fmaf(0.045f, Cpavg, 1.0f);
    float SH = fmaf(0.015f, Cpavg * T, 1.0f);

    // merged divides: one rcp
    float pSCSH = SC * SH;
    float pSLSH = SL * SH;
    float pSLSC = SL * SC;
    float D = frcp_a(pSLSC * SH);
    float xx = dL * (pSCSH * D);
    float yy = dC * (pSLSH * D);
    float zz = dH * (pSLSC * D);
    return fsqrt_a(fmaf(xx, xx, fmaf(yy, yy, fmaf(zz, zz, RT * yy * zz))));
}

__device__ __forceinline__ float row_loss(const float* __restrict__ stab,
                                          const float* __restrict__ ftab,
                                          const __half2* __restrict__ httab,
                                          float pr, float pg, float pb,
                                          float tr, float tg, float tb) {
    float d0 = pr - tr, d1 = pg - tg, d2 = pb - tb;
    float sumd2 = fmaf(d0, d0, fmaf(d1, d1, d2 * d2));
    float L1, A1, B1, L2, A2, B2;
    rgb2lab(stab, ftab, pr, pg, pb, L1, A1, B1);
    rgb2lab(stab, ftab, tr, tg, tb, L2, A2, B2);
    float de = delta_e_2000(httab, L1, A1, B1, L2, A2, B2);
    return fmaf(sumd2, 0.2f / 3.0f, 0.8f * de);
}

__global__ void __launch_bounds__(THREADS, 6)
de_loss_kernel(const float* __restrict__ pred, const float* __restrict__ targ,
               float* __restrict__ out, int n, float inv_n) {
    __shared__ float   s_srgb[SRGB_N];
    __shared__ float   s_labf[LABF_N];
    __shared__ __half2 s_ht[HT_N];

    {
        const float4* gs = reinterpret_cast<const float4*>(g_srgb_tab);
        float4* ss = reinterpret_cast<float4*>(s_srgb);
        for (int i = threadIdx.x; i < SRGB_N / 4; i += THREADS) ss[i] = gs[i];
        const float4* gf = reinterpret_cast<const float4*>(g_labf_tab);
        float4* sf = reinterpret_cast<float4*>(s_labf);
        for (int i = threadIdx.x; i < LABF_N / 4; i += THREADS) sf[i] = gf[i];
        const float4* gh = reinterpret_cast<const float4*>(g_ht_tab);
        float4* shh = reinterpret_cast<float4*>(s_ht);
        for (int i = threadIdx.x; i < HT_N / 4; i += THREADS) shh[i] = gh[i];
    }
    __syncthreads();

    const int P = gridDim.x * blockDim.x;
    const int tid = blockIdx.x * blockDim.x + threadIdx.x;
    float acc = 0.0f;

    for (int base = tid * 4; base + 3 < n; base += P * 4) {
        const float4* p4 = reinterpret_cast<const float4*>(pred + (size_t)base * 3);
        const float4* t4 = reinterpret_cast<const float4*>(targ + (size_t)base * 3);
        float4 p0 = p4[0], p1 = p4[1], p2 = p4[2];
        float4 q0 = t4[0], q1 = t4[1], q2 = t4[2];

        acc += row_loss(s_srgb, s_labf, s_ht, p0.x, p0.y, p0.z,  q0.x, q0.y, q0.z);
        acc += row_loss(s_srgb, s_labf, s_ht, p0.w, p1.x, p1.y,  q0.w, q1.x, q1.y);
        acc += row_loss(s_srgb, s_labf, s_ht, p1.z, p1.w, p2.x,  q1.z, q1.w, q2.x);
        acc += row_loss(s_srgb, s_labf, s_ht, p2.y, p2.z, p2.w,  q2.y, q2.z, q2.w);
    }
    int tail_start = (n / (P * 4)) * (P * 4);
    for (int i = tail_start + tid; i < n; i += P) {
        const float* p = pred + (size_t)i * 3;
        const float* t = targ + (size_t)i * 3;
        acc += row_loss(s_srgb, s_labf, s_ht, p[0], p[1], p[2], t[0], t[1], t[2]);
    }

    float v = warp_reduce(acc);
    __shared__ float sh[THREADS / 32];
    int lane = threadIdx.x & 31;
    int wid = threadIdx.x >> 5;
    if (lane == 0) sh[wid] = v;
    __syncthreads();
    if (wid == 0) {
        v = (lane < THREADS / 32) ? sh[lane] : 0.0f;
        v = warp_reduce(v);
        if (lane == 0) g_partials[blockIdx.x] = v;
    }

    __shared__ bool is_last;
    __threadfence();
    if (threadIdx.x == 0) {
        unsigned int c = atomicAdd(&g_count, 1u);
        is_last = (c == gridDim.x - 1);
    }
    __syncthreads();
    if (is_last) {
        float a = 0.0f;
        for (int i = threadIdx.x; i < BLOCKS; i += THREADS) a += g_partials[i];
        float w = warp_reduce(a);
        if (lane == 0) sh[wid] = w;
        __syncthreads();
        if (wid == 0) {
            w = (lane < THREADS / 32) ? sh[lane] : 0.0f;
            w = warp_reduce(w);
            if (lane == 0) {
                out[0] = w * inv_n;
                g_count = 0;
            }
        }
    }
}

extern "C" void kernel_launch(void* const* d_in, const int* in_sizes, int n_in,
                              void* d_out, int out_size) {
    const float* pred = (const float*)d_in[0];
    const float* targ = (const float*)d_in[1];
    int n = in_sizes[0] / 3;
    init_tables_kernel<<<(LABF_N + 255) / 256, 256>>>();
    de_loss_kernel<<<BLOCKS, THREADS>>>(pred, targ, (float*)d_out, n, 1.0f / (float)n);
}